// round 14
// baseline (speedup 1.0000x reference)
#include <cuda_runtime.h>
#include <cuda_fp16.h>
#include <cstdint>
#include <math.h>

#define BATCH 64
#define WPOS  2048
#define NPOS  (BATCH * WPOS)      // 131072 positions
#define CH    64
#define MTILE 64                  // positions per tile (kernel A)
#define NTILES (NPOS / MTILE)     // 2048
#define GRID_A 148                // persistent blocks (1/SM)
#define THR_A  512                // 2 groups x 256
#define KC    128                 // K chunk for dense split-K
#define FLATK (WPOS * CH)         // 131072
#define GSPLIT (FLATK / KC)       // 1024
#define NW    192                 // gates i,g,o (f gate dead)
#define RCH   32                  // red1 chunks

// ---- scratch (device globals; no allocation allowed) -----------------------
__device__ __align__(16) float g_h4[(size_t)NPOS * CH];            // 32 MB
__device__ __align__(16) float g_part[(size_t)GSPLIT * 64 * 64];   // 16 MB
__device__ __align__(16) float g_red[RCH * 64 * 64];               // 512 KB
__device__ __align__(16) unsigned short g_Wh[4][NW * 64];          // pre-swizzled fp16 weights
__device__ __align__(16) float g_Bp[4][NW];

typedef unsigned long long u64;

__device__ __forceinline__ float hsig(float v) {
    return __saturatef(fmaf(v, 0.2f, 0.5f));
}
__device__ __forceinline__ float tanh_fast(float v) {   // MUFU.TANH, sm_75+
    float r; asm("tanh.approx.f32 %0,%1;" : "=f"(r) : "f"(v)); return r;
}
__device__ __forceinline__ uint32_t smem_u32(const void* p) {
    uint32_t a;
    asm("{ .reg .u64 t; cvta.to.shared.u64 t, %1; cvt.u32.u64 %0, t; }" : "=r"(a) : "l"(p));
    return a;
}
#define GBAR(id) asm volatile("bar.sync %0, 256;" :: "r"(id) : "memory")

// warp-level fp16 mma + ldmatrix (plain sm_80+ PTX; tcgen05 is 'a'-gated)
__device__ __forceinline__ void mma16816(float* c, const uint32_t* a, uint32_t b0, uint32_t b1) {
    asm volatile(
        "mma.sync.aligned.m16n8k16.row.col.f32.f16.f16.f32 "
        "{%0,%1,%2,%3},{%4,%5,%6,%7},{%8,%9},{%0,%1,%2,%3};"
        : "+f"(c[0]), "+f"(c[1]), "+f"(c[2]), "+f"(c[3])
        : "r"(a[0]), "r"(a[1]), "r"(a[2]), "r"(a[3]), "r"(b0), "r"(b1));
}
#define LDSM_X4(r, a) \
    asm volatile("ldmatrix.sync.aligned.m8n8.x4.shared.b16 {%0,%1,%2,%3}, [%4];" \
        : "=r"((r)[0]), "=r"((r)[1]), "=r"((r)[2]), "=r"((r)[3]) : "r"(a))

__device__ __forceinline__ unsigned short f2h(float a) {
    return __half_as_ushort(__float2half_rn(a));
}
__device__ __forceinline__ float h2f(unsigned short a) {
    return __half2float(__ushort_as_half(a));
}
__device__ __forceinline__ u64 pack4hf(float a, float b, float c, float d) {
    return (u64)f2h(a) | ((u64)f2h(b) << 16) | ((u64)f2h(c) << 32) | ((u64)f2h(d) << 48);
}
__device__ __forceinline__ uint32_t pk2hf(float a, float b) {
    return (uint32_t)f2h(a) | ((uint32_t)f2h(b) << 16);
}

// lstm4 smem layout (bytes): 4 fp16 weight images + 2 groups x 2 ping-pong A bufs + bias
#define WOFF   0                        // 4 x 24576 fp16 [192n][64k] XOR-swz
#define WLSZ   24576
#define ABUF   (4 * WLSZ)               // 98304: grp stride 32768, buf stride 16384
#define BIAS   (ABUF + 65536)           // 163840: 4*192 f32
#define SMEM_A_TOT 166912

// ---------------------------------------------------------------------------
// Prep (split into 3 launches so k_lstm4 lands at captured launch slot #4):
// fp16 weight slices, GATE-INTERLEAVED n-order for 48-col n-quarters:
//   n = q*48 + j*24 + gate*8 + e  ->  channel c = q*16 + j*8 + e
// XOR row swizzle pre-applied so blocks copy verbatim.
// ---------------------------------------------------------------------------
__global__ void k_prep_w(const float* __restrict__ Wa, const float* __restrict__ Wb,
                         int lbase)
{
    const int l = lbase + blockIdx.x, tid = threadIdx.x;
    const float* W = (blockIdx.x == 0) ? Wa : Wb;
    for (int idx = tid; idx < NW * 64; idx += 256) {
        int n = idx >> 6, k = idx & 63;
        int q = n / 48, r = n % 48;
        int j = r / 24, gate = (r % 24) >> 3, e = r & 7;
        int c = q * 16 + j * 8 + e;
        int gn = (gate == 0) ? c : (gate == 1) ? 128 + c : 192 + c;   // skip dead f gate
        uint32_t sw = (uint32_t)n * 64 + ((((uint32_t)(2 * k)) ^ (((uint32_t)n & 7) << 4)) >> 1);
        g_Wh[l][sw] = f2h(W[k * 256 + gn]);
    }
}
__global__ void k_prep_b(const float* __restrict__ B0, const float* __restrict__ B1,
                         const float* __restrict__ B2, const float* __restrict__ B3)
{
    const int tid = threadIdx.x;
    for (int idx = tid; idx < 4 * NW; idx += 256) {
        int l = idx / NW, n = idx % NW;
        const float* Bb = (l == 0) ? B0 : (l == 1) ? B1 : (l == 2) ? B2 : B3;
        int q = n / 48, r = n % 48;
        int j = r / 24, gate = (r % 24) >> 3, e = r & 7;
        int c = q * 16 + j * 8 + e;
        int gn = (gate == 0) ? c : (gate == 1) ? 128 + c : 192 + c;
        g_Bp[l][n] = Bb[gn];
    }
}

// ---------------------------------------------------------------------------
// Kernel A: persistent fused 4x ConvLSTM via mma.sync fp16 2-pass.
// 148 blocks x 512 threads = two independent 8-warp pipelines (named barriers).
// Warp tile 32m x 48n; B fragments held in regs across both A passes.
// ---------------------------------------------------------------------------
__global__ void __launch_bounds__(THR_A, 1) k_lstm4(const float* __restrict__ x)
{
    extern __shared__ char sm[];
    const uint32_t sb = smem_u32(sm);
    const int tid = threadIdx.x;
    const int wid = tid >> 5, lane = tid & 31;
    const int grp = tid >> 8;            // barrier group 0/1
    const int tig256 = tid & 255;        // tid within group
    const int g8 = lane >> 2, tig = lane & 3;

    // one-time: weights (96KB) + biases -> smem (all 512 threads)
    {
        const uint4* src = (const uint4*)g_Wh;
        uint4* dst = (uint4*)(sm + WOFF);
        #pragma unroll
        for (int i = 0; i < 12; ++i) dst[tid + i * THR_A] = src[tid + i * THR_A];
        float* bsw = (float*)(sm + BIAS);
        #pragma unroll
        for (int i = 0; i < 2; ++i) {
            int idx = tid + i * THR_A;
            if (idx < 4 * NW) bsw[idx] = ((const float*)g_Bp)[idx];
        }
    }
    __syncthreads();                     // weights immutable hereafter
    const float* bs = (const float*)(sm + BIAS);

    // group-local warp layout: 8 warps = 2 m-groups (32 rows) x 4 n-quarters (48 cols)
    const int wg = wid & 7;
    const int lt = lane >> 3, lr = lane & 7;
    const int mgrp = wg & 1, nq = wg >> 1;
    const int mrow = mgrp * 32, n0 = nq * 48, chb = nq * 16;
    const uint32_t AG = ABUF + (uint32_t)grp * 32768;   // group's buffer base
    const int arow = mrow + ((lt & 1) << 3) + lr;
    const uint32_t a_rowoff = (uint32_t)arow * 128;
    const uint32_t aswz = ((uint32_t)arow & 7) << 4;
    const int akadd = (lt >> 1) << 4;
    const int brow0 = n0 + ((lt >> 1) << 3) + lr;
    const uint32_t b_rowoff0 = (uint32_t)brow0 * 128;
    const uint32_t bswz = ((uint32_t)brow0 & 7) << 4;
    const int bkadd = (lt & 1) << 4;
    const int bar = grp + 1;

    for (int t = blockIdx.x * 2 + grp; t < NTILES; t += GRID_A * 2) {
        // stage input tile into buf0 (hi at +0, lo at +8192); overlaps prev L3
        {
            const float4* xin = (const float4*)(x + (size_t)t * MTILE * CH);
            #pragma unroll
            for (int i = 0; i < 4; ++i) {
                int fi = tig256 + i * 256;          // 1024 float4
                int pos = fi >> 4, c = (fi & 15) << 2;
                float4 v = xin[fi];
                uint32_t b = (uint32_t)pos * 128 + (((uint32_t)(2 * c)) ^ (((uint32_t)pos & 7) << 4));
                *(u64*)(sm + AG + b) = pack4hf(v.x, v.y, v.z, v.w);
                *(u64*)(sm + AG + 8192 + b) = pack4hf(
                    v.x - h2f(f2h(v.x)), v.y - h2f(f2h(v.y)),
                    v.z - h2f(f2h(v.z)), v.w - h2f(f2h(v.w)));
            }
        }
        GBAR(bar);

        #pragma unroll 1
        for (int l = 0; l < 4; ++l) {
            const uint32_t rbuf = AG + (uint32_t)(l & 1) * 16384;        // read buf
            const uint32_t wbuf = AG + (uint32_t)((l + 1) & 1) * 16384;  // write buf

            float acc[2][6][4];
            #pragma unroll
            for (int mi = 0; mi < 2; ++mi)
                #pragma unroll
                for (int nt = 0; nt < 6; ++nt)
                    #pragma unroll
                    for (int r = 0; r < 4; ++r) acc[mi][nt][r] = 0.f;

            const uint32_t Babs = sb + WOFF + (uint32_t)l * WLSZ + b_rowoff0;
            #pragma unroll
            for (int ks = 0; ks < 4; ++ks) {
                const uint32_t kb = ks * 32;
                uint32_t b[3][4];   // B held across both A passes
                #pragma unroll
                for (int np = 0; np < 3; ++np)
                    LDSM_X4(b[np], Babs + (uint32_t)np * 2048 + ((kb + bkadd) ^ bswz));
                #pragma unroll
                for (int s = 0; s < 2; ++s) {
                    const uint32_t Aabs = sb + rbuf + (uint32_t)s * 8192 + a_rowoff;
                    const uint32_t ka = (kb + akadd) ^ aswz;
                    uint32_t a0[4], a1[4];
                    LDSM_X4(a0, Aabs + ka);
                    LDSM_X4(a1, Aabs + 2048 + ka);     // +16 rows, same swizzle
                    #pragma unroll
                    for (int np = 0; np < 3; ++np) {
                        mma16816(acc[0][2 * np],     a0, b[np][0], b[np][1]);
                        mma16816(acc[0][2 * np + 1], a0, b[np][2], b[np][3]);
                        mma16816(acc[1][2 * np],     a1, b[np][0], b[np][1]);
                        mma16816(acc[1][2 * np + 1], a1, b[np][2], b[np][3]);
                    }
                }
            }

            // register gate epilogue: per mi, frags [3j]=i, [3j+1]=g, [3j+2]=o
            float hreg[2][2][4];
            const float* bl = bs + l * NW + n0 + 2 * tig;
            #pragma unroll
            for (int mi = 0; mi < 2; ++mi) {
                #pragma unroll
                for (int j = 0; j < 2; ++j) {
                    float2 bi = *(const float2*)(bl + j * 24);
                    float2 bg = *(const float2*)(bl + j * 24 + 8);
                    float2 bo = *(const float2*)(bl + j * 24 + 16);
                    const float* ai = acc[mi][3 * j];
                    const float* ag = acc[mi][3 * j + 1];
                    const float* ao = acc[mi][3 * j + 2];
                    hreg[mi][j][0] = hsig(ao[0] + bo.x) * tanh_fast(hsig(ai[0] + bi.x) * tanh_fast(ag[0] + bg.x));
                    hreg[mi][j][1] = hsig(ao[1] + bo.y) * tanh_fast(hsig(ai[1] + bi.y) * tanh_fast(ag[1] + bg.y));
                    hreg[mi][j][2] = hsig(ao[2] + bo.x) * tanh_fast(hsig(ai[2] + bi.x) * tanh_fast(ag[2] + bg.x));
                    hreg[mi][j][3] = hsig(ao[3] + bo.y) * tanh_fast(hsig(ai[3] + bi.y) * tanh_fast(ag[3] + bg.y));
                }
            }

            if (l < 3) {
                // ping-pong: write into wbuf (untouched by this layer's reads)
                #pragma unroll
                for (int mi = 0; mi < 2; ++mi) {
                    const int m1 = mrow + mi * 16 + g8, m2 = m1 + 8;
                    #pragma unroll
                    for (int j = 0; j < 2; ++j) {
                        int c0 = chb + j * 8 + 2 * tig;
                        const float* h = hreg[mi][j];
                        float r00 = h[0] - h2f(f2h(h[0]));
                        float r01 = h[1] - h2f(f2h(h[1]));
                        float r10 = h[2] - h2f(f2h(h[2]));
                        float r11 = h[3] - h2f(f2h(h[3]));
                        uint32_t b1o = (uint32_t)m1 * 128 + (((uint32_t)(2 * c0)) ^ (((uint32_t)m1 & 7) << 4));
                        uint32_t b2o = (uint32_t)m2 * 128 + (((uint32_t)(2 * c0)) ^ (((uint32_t)m2 & 7) << 4));
                        *(uint32_t*)(sm + wbuf + b1o) = pk2hf(h[0], h[1]);
                        *(uint32_t*)(sm + wbuf + 8192 + b1o) = pk2hf(r00, r01);
                        *(uint32_t*)(sm + wbuf + b2o) = pk2hf(h[2], h[3]);
                        *(uint32_t*)(sm + wbuf + 8192 + b2o) = pk2hf(r10, r11);
                    }
                }
                GBAR(bar);   // writes visible before next layer's reads
            } else {
                const size_t p0 = (size_t)t * MTILE;
                #pragma unroll
                for (int mi = 0; mi < 2; ++mi) {
                    const int m1 = mrow + mi * 16 + g8, m2 = m1 + 8;
                    #pragma unroll
                    for (int j = 0; j < 2; ++j) {
                        int c0 = chb + j * 8 + 2 * tig;
                        const float* h = hreg[mi][j];
                        *(float2*)&g_h4[(p0 + m1) * CH + c0] = make_float2(h[0], h[1]);
                        *(float2*)&g_h4[(p0 + m2) * CH + c0] = make_float2(h[2], h[3]);
                    }
                }
            }
        }
    }
}

// ---------------------------------------------------------------------------
// Kernel B: split-K GEMM via fp16 mma, 3-pass (AhBh + AlBh + AhBl ~ fp32-exact):
// partial[g] = flat[:, kb:kb+128] @ D1w[kb:kb+128, :].  M=64(batch) N=64 K=128.
// ---------------------------------------------------------------------------
#define DAH 0
#define DAL 16384
#define DBH 32768
#define DBL 49152
#define SMEM_B_TOT 65536

__global__ void __launch_bounds__(256) k_dense_split(const float* __restrict__ D1w)
{
    extern __shared__ char smf[];
    const uint32_t sb = smem_u32(smf);
    const int tid = threadIdx.x, wid = tid >> 5, lane = tid & 31;
    const size_t kbase = (size_t)blockIdx.x * KC;

    // A: g_h4 [64 b][128 k] fp32 -> hi/lo fp16, rows 256B, XOR swz
    #pragma unroll
    for (int i = 0; i < 8; ++i) {
        int fi = tid + i * 256;                 // 2048 float4
        int b = fi >> 5, kq = fi & 31;          // k = kq*4
        float4 v = *(const float4*)(g_h4 + (size_t)b * FLATK + kbase + (size_t)kq * 4);
        uint32_t off = (uint32_t)b * 256 + (((uint32_t)(kq * 8)) ^ (((uint32_t)b & 7) << 4));
        *(u64*)(smf + DAH + off) = pack4hf(v.x, v.y, v.z, v.w);
        *(u64*)(smf + DAL + off) = pack4hf(
            v.x - h2f(f2h(v.x)), v.y - h2f(f2h(v.y)),
            v.z - h2f(f2h(v.z)), v.w - h2f(f2h(v.w)));
    }
    // B: D1w [128 k][64 n] fp32 -> transpose to [64 n][128 k] hi/lo fp16
    #pragma unroll
    for (int i = 0; i < 8; ++i) {
        int fi = tid + i * 256;                 // 2048 float4
        int k = fi >> 4, n4 = (fi & 15) << 2;
        float4 v = ((const float4*)(D1w + (kbase + k) * 64))[fi & 15];
        float vv[4] = {v.x, v.y, v.z, v.w};
        #pragma unroll
        for (int e = 0; e < 4; ++e) {
            int n = n4 + e;
            uint32_t off = (uint32_t)n * 256 + (((uint32_t)(2 * k)) ^ (((uint32_t)n & 7) << 4));
            unsigned short hh = f2h(vv[e]);
            *(unsigned short*)(smf + DBH + off) = hh;
            *(unsigned short*)(smf + DBL + off) = f2h(vv[e] - h2f(hh));
        }
    }
    __syncthreads();

    // 8 warps: mw 0..3 (16 batch rows), nw 0..1 (32 n cols)
    const int mw = wid & 3, nw = wid >> 2;
    const int lt = lane >> 3, lr = lane & 7;
    const int g8 = lane >> 2, tig = lane & 3;
    const int arow = mw * 16 + ((lt & 1) << 3) + lr;
    const uint32_t a_ro = (uint32_t)arow * 256, aswz = ((uint32_t)arow & 7) << 4;
    const int akadd = (lt >> 1) << 4;
    const int brow = nw * 32 + ((lt >> 1) << 3) + lr;
    const uint32_t b_ro = (uint32_t)brow * 256, bswz = ((uint32_t)brow & 7) << 4;
    const int bkadd = (lt & 1) << 4;

    float acc[4][4];
    #pragma unroll
    for (int nf = 0; nf < 4; ++nf)
        #pragma unroll
        for (int r = 0; r < 4; ++r) acc[nf][r] = 0.f;

    #pragma unroll
    for (int ks = 0; ks < 8; ++ks) {
        const uint32_t kb = ks * 32;
        const uint32_t ka = (kb + akadd) ^ aswz;
        const uint32_t kbb = (kb + bkadd) ^ bswz;
        uint32_t ah[4], al[4], bh0[4], bh1[4], bl0[4], bl1[4];
        LDSM_X4(ah, sb + DAH + a_ro + ka);
        LDSM_X4(al, sb + DAL + a_ro + ka);
        LDSM_X4(bh0, sb + DBH + b_ro + kbb);
        LDSM_X4(bh1, sb + DBH + b_ro + 4096 + kbb);   // +16 n rows
        LDSM_X4(bl0, sb + DBL + b_ro + kbb);
        LDSM_X4(bl1, sb + DBL + b_ro + 4096 + kbb);
        mma16816(acc[0], ah, bh0[0], bh0[1]);
        mma16816(acc[1], ah, bh0[2], bh0[3]);
        mma16816(acc[2], ah, bh1[0], bh1[1]);
        mma16816(acc[3], ah, bh1[2], bh1[3]);
        mma16816(acc[0], al, bh0[0], bh0[1]);
        mma16816(acc[1], al, bh0[2], bh0[3]);
        mma16816(acc[2], al, bh1[0], bh1[1]);
        mma16816(acc[3], al, bh1[2], bh1[3]);
        mma16816(acc[0], ah, bl0[0], bl0[1]);
        mma16816(acc[1], ah, bl0[2], bl0[3]);
        mma16816(acc[2], ah, bl1[0], bl1[1]);
        mma16816(acc[3], ah, bl1[2], bl1[3]);
    }

    float* dst = g_part + (size_t)blockIdx.x * 4096;
    const int m1 = mw * 16 + g8, m2 = m1 + 8;
    #pragma unroll
    for (int nf = 0; nf < 4; ++nf) {
        int n = nw * 32 + nf * 8 + 2 * tig;
        *(float2*)&dst[m1 * 64 + n] = make_float2(acc[nf][0], acc[nf][1]);
        *(float2*)&dst[m2 * 64 + n] = make_float2(acc[nf][2], acc[nf][3]);
    }
}

// ---------------------------------------------------------------------------
// Kernel C1: stage-1 reduce: 2048 blocks, each sums 32 g-slices for (b,chunk).
// ---------------------------------------------------------------------------
__global__ void k_red1()
{
    __shared__ float sred[256];
    const int blk = blockIdx.x;            // 2048 = 64 b x 32 chunks
    const int b = blk >> 5, chunk = blk & 31;
    const int tid = threadIdx.x;
    const int n = tid & 63, sub = tid >> 6;
    const float* p = g_part + (size_t)(chunk * 32 + sub * 8) * 4096 + (size_t)b * 64 + n;
    float s = 0.f;
    #pragma unroll
    for (int t = 0; t < 8; ++t) s += p[(size_t)t * 4096];
    sred[tid] = s;
    __syncthreads();
    if (tid < 64)
        g_red[chunk * 4096 + b * 64 + n] =
            sred[tid] + sred[tid + 64] + sred[tid + 128] + sred[tid + 192];
}

// ---------------------------------------------------------------------------
// Kernel C2: final: sum 32 chunks + D1b + relu + D2 GEMV. 64 blocks x 64 thr.
// ---------------------------------------------------------------------------
__global__ void k_final(const float* __restrict__ D1b, const float* __restrict__ D2w,
                        const float* __restrict__ D2b, float* __restrict__ out)
{
    __shared__ float sA[2];
    const int b = blockIdx.x, n = threadIdx.x;   // 64 threads
    float v = 0.f;
    #pragma unroll
    for (int ch = 0; ch < RCH; ++ch) v += g_red[ch * 4096 + b * 64 + n];
    float y = fmaxf(v + D1b[n], 0.f) * D2w[n];
    #pragma unroll
    for (int off = 16; off > 0; off >>= 1)
        y += __shfl_down_sync(0xffffffffu, y, off);
    if ((n & 31) == 0) sA[n >> 5] = y;
    __syncthreads();
    if (n == 0) out[b] = sA[0] + sA[1] + D2b[0];
}

// ---------------------------------------------------------------------------
extern "C" void kernel_launch(void* const* d_in, const int* in_sizes, int n_in,
                              void* d_out, int out_size)
{
    const float* x   = (const float*)d_in[0];
    const float* W1x = (const float*)d_in[1];
    const float* b1  = (const float*)d_in[3];
    const float* W2x = (const float*)d_in[4];
    const float* b2  = (const float*)d_in[6];
    const float* W3x = (const float*)d_in[7];
    const float* b3  = (const float*)d_in[9];
    const float* W4x = (const float*)d_in[10];
    const float* b4  = (const float*)d_in[12];
    const float* D1w = (const float*)d_in[13];
    const float* D1b = (const float*)d_in[14];
    const float* D2w = (const float*)d_in[15];
    const float* D2b = (const float*)d_in[16];

    cudaFuncSetAttribute(k_lstm4, cudaFuncAttributeMaxDynamicSharedMemorySize, SMEM_A_TOT);
    cudaFuncSetAttribute(k_dense_split, cudaFuncAttributeMaxDynamicSharedMemorySize, SMEM_B_TOT);

    // SAME padding over H=1 picks exactly one kernel row: r=4 (kh=10), r=2 (kh=5)
    // prep split into 3 launches so k_lstm4 is launch #4 (ncu-captured slot).
    k_prep_w<<<2, 256>>>(W1x + 4 * 64 * 256, W2x + 2 * 64 * 256, 0);
    k_prep_w<<<2, 256>>>(W3x + 4 * 64 * 256, W4x + 2 * 64 * 256, 2);
    k_prep_b<<<1, 256>>>(b1, b2, b3, b4);
    k_lstm4<<<GRID_A, THR_A, SMEM_A_TOT>>>(x);
    k_dense_split<<<GSPLIT, 256, SMEM_B_TOT>>>(D1w);
    k_red1<<<2048, 256>>>();
    k_final<<<BATCH, 64>>>(D1b, D2w, D2b, (float*)d_out);
}

// round 15
// speedup vs baseline: 1.0942x; 1.0942x over previous
#include <cuda_runtime.h>
#include <cuda_fp16.h>
#include <cstdint>
#include <math.h>

#define BATCH 64
#define WPOS  2048
#define NPOS  (BATCH * WPOS)      // 131072 positions
#define CH    64
#define MTILE 64                  // positions per tile (kernel A)
#define NTILES (NPOS / MTILE)     // 2048
#define GRID_A 148                // persistent blocks (1/SM)
#define THR_A  512                // 2 groups x 256
#define KC    128                 // K chunk for dense split-K
#define FLATK (WPOS * CH)         // 131072
#define GSPLIT (FLATK / KC)       // 1024
#define NW    192                 // gates i,g,o (f gate dead)
#define RCH   32                  // red1 chunks

// ---- scratch (device globals; no allocation allowed) -----------------------
__device__ __align__(16) float g_h4[(size_t)NPOS * CH];            // 32 MB
__device__ __align__(16) float g_part[(size_t)GSPLIT * 64 * 64];   // 16 MB
__device__ __align__(16) float g_red[RCH * 64 * 64];               // 512 KB
__device__ __align__(16) unsigned short g_Wh[4][NW * 64];          // pre-swizzled fp16 weights
__device__ __align__(16) float g_Bp[4][NW];

typedef unsigned long long u64;

__device__ __forceinline__ float hsig(float v) {
    return __saturatef(fmaf(v, 0.2f, 0.5f));
}
__device__ __forceinline__ float tanh_fast(float v) {   // MUFU.TANH, sm_75+
    float r; asm("tanh.approx.f32 %0,%1;" : "=f"(r) : "f"(v)); return r;
}
__device__ __forceinline__ uint32_t smem_u32(const void* p) {
    uint32_t a;
    asm("{ .reg .u64 t; cvta.to.shared.u64 t, %1; cvt.u32.u64 %0, t; }" : "=r"(a) : "l"(p));
    return a;
}
#define GBAR(id) asm volatile("bar.sync %0, 256;" :: "r"(id) : "memory")

// warp-level fp16 mma + ldmatrix (plain sm_80+ PTX; tcgen05 is 'a'-gated)
__device__ __forceinline__ void mma16816(float* c, const uint32_t* a, uint32_t b0, uint32_t b1) {
    asm volatile(
        "mma.sync.aligned.m16n8k16.row.col.f32.f16.f16.f32 "
        "{%0,%1,%2,%3},{%4,%5,%6,%7},{%8,%9},{%0,%1,%2,%3};"
        : "+f"(c[0]), "+f"(c[1]), "+f"(c[2]), "+f"(c[3])
        : "r"(a[0]), "r"(a[1]), "r"(a[2]), "r"(a[3]), "r"(b0), "r"(b1));
}
#define LDSM_X4(r, a) \
    asm volatile("ldmatrix.sync.aligned.m8n8.x4.shared.b16 {%0,%1,%2,%3}, [%4];" \
        : "=r"((r)[0]), "=r"((r)[1]), "=r"((r)[2]), "=r"((r)[3]) : "r"(a))

__device__ __forceinline__ unsigned short f2h(float a) {
    return __half_as_ushort(__float2half_rn(a));
}
__device__ __forceinline__ float h2f(unsigned short a) {
    return __half2float(__ushort_as_half(a));
}
__device__ __forceinline__ u64 pack4hf(float a, float b, float c, float d) {
    return (u64)f2h(a) | ((u64)f2h(b) << 16) | ((u64)f2h(c) << 32) | ((u64)f2h(d) << 48);
}
__device__ __forceinline__ uint32_t pk2hf(float a, float b) {
    return (uint32_t)f2h(a) | ((uint32_t)f2h(b) << 16);
}

// lstm4 smem layout (bytes): 4 fp16 weight images + 2 groups x 2 ping-pong A bufs + bias
#define WOFF   0                        // 4 x 24576 fp16 [192n][64k] XOR-swz
#define WLSZ   24576
#define ABUF   (4 * WLSZ)               // 98304: grp stride 32768, buf stride 16384
#define BIAS   (ABUF + 65536)           // 163840: 4*192 f32
#define SMEM_A_TOT 166912

// ---------------------------------------------------------------------------
// Prep: fp16 weight slices, GATE-INTERLEAVED n-order for 48-col n-quarters:
//   n = q*48 + j*24 + gate*8 + e  ->  channel c = q*16 + j*8 + e
// XOR row swizzle pre-applied so blocks copy verbatim.
// ---------------------------------------------------------------------------
__global__ void k_prep(const float* __restrict__ W0, const float* __restrict__ W1,
                       const float* __restrict__ W2, const float* __restrict__ W3,
                       const float* __restrict__ B0, const float* __restrict__ B1,
                       const float* __restrict__ B2, const float* __restrict__ B3)
{
    const int l = blockIdx.x, tid = threadIdx.x;
    const float* W  = (l == 0) ? W0 : (l == 1) ? W1 : (l == 2) ? W2 : W3;
    const float* Bb = (l == 0) ? B0 : (l == 1) ? B1 : (l == 2) ? B2 : B3;
    for (int idx = tid; idx < NW * 64; idx += 256) {
        int n = idx >> 6, k = idx & 63;
        int q = n / 48, r = n % 48;
        int j = r / 24, gate = (r % 24) >> 3, e = r & 7;
        int c = q * 16 + j * 8 + e;
        int gn = (gate == 0) ? c : (gate == 1) ? 128 + c : 192 + c;   // skip dead f gate
        uint32_t sw = (uint32_t)n * 64 + ((((uint32_t)(2 * k)) ^ (((uint32_t)n & 7) << 4)) >> 1);
        g_Wh[l][sw] = f2h(W[k * 256 + gn]);
    }
    for (int n = tid; n < NW; n += 256) {
        int q = n / 48, r = n % 48;
        int j = r / 24, gate = (r % 24) >> 3, e = r & 7;
        int c = q * 16 + j * 8 + e;
        int gn = (gate == 0) ? c : (gate == 1) ? 128 + c : 192 + c;
        g_Bp[l][n] = Bb[gn];
    }
}

// ---------------------------------------------------------------------------
// Kernel A: persistent fused 4x ConvLSTM via mma.sync fp16 2-pass.
// 148 blocks x 512 threads = two independent 8-warp pipelines (named barriers).
// Warp tile 32m x 48n. Each ks iteration: ALL 7 LDSM issued up front, then
// 24 mma -> ptxas can rotate next iteration's independent loads into the
// mma shadow (software pipeline).
// ---------------------------------------------------------------------------
__global__ void __launch_bounds__(THR_A, 1) k_lstm4(const float* __restrict__ x)
{
    extern __shared__ char sm[];
    const uint32_t sb = smem_u32(sm);
    const int tid = threadIdx.x;
    const int wid = tid >> 5, lane = tid & 31;
    const int grp = tid >> 8;            // barrier group 0/1
    const int tig256 = tid & 255;        // tid within group
    const int g8 = lane >> 2, tig = lane & 3;

    // one-time: weights (96KB) + biases -> smem (all 512 threads)
    {
        const uint4* src = (const uint4*)g_Wh;
        uint4* dst = (uint4*)(sm + WOFF);
        #pragma unroll
        for (int i = 0; i < 12; ++i) dst[tid + i * THR_A] = src[tid + i * THR_A];
        float* bsw = (float*)(sm + BIAS);
        #pragma unroll
        for (int i = 0; i < 2; ++i) {
            int idx = tid + i * THR_A;
            if (idx < 4 * NW) bsw[idx] = ((const float*)g_Bp)[idx];
        }
    }
    __syncthreads();                     // weights immutable hereafter
    const float* bs = (const float*)(sm + BIAS);

    // group-local warp layout: 8 warps = 2 m-groups (32 rows) x 4 n-quarters (48 cols)
    const int wg = wid & 7;
    const int lt = lane >> 3, lr = lane & 7;
    const int mgrp = wg & 1, nq = wg >> 1;
    const int mrow = mgrp * 32, n0 = nq * 48, chb = nq * 16;
    const uint32_t AG = ABUF + (uint32_t)grp * 32768;   // group's buffer base
    const int arow = mrow + ((lt & 1) << 3) + lr;
    const uint32_t a_rowoff = (uint32_t)arow * 128;
    const uint32_t aswz = ((uint32_t)arow & 7) << 4;
    const int akadd = (lt >> 1) << 4;
    const int brow0 = n0 + ((lt >> 1) << 3) + lr;
    const uint32_t b_rowoff0 = (uint32_t)brow0 * 128;
    const uint32_t bswz = ((uint32_t)brow0 & 7) << 4;
    const int bkadd = (lt & 1) << 4;
    const int bar = grp + 1;

    for (int t = blockIdx.x * 2 + grp; t < NTILES; t += GRID_A * 2) {
        // stage input tile into buf0 (hi at +0, lo at +8192); overlaps prev L3
        {
            const float4* xin = (const float4*)(x + (size_t)t * MTILE * CH);
            #pragma unroll
            for (int i = 0; i < 4; ++i) {
                int fi = tig256 + i * 256;          // 1024 float4
                int pos = fi >> 4, c = (fi & 15) << 2;
                float4 v = xin[fi];
                uint32_t b = (uint32_t)pos * 128 + (((uint32_t)(2 * c)) ^ (((uint32_t)pos & 7) << 4));
                *(u64*)(sm + AG + b) = pack4hf(v.x, v.y, v.z, v.w);
                *(u64*)(sm + AG + 8192 + b) = pack4hf(
                    v.x - h2f(f2h(v.x)), v.y - h2f(f2h(v.y)),
                    v.z - h2f(f2h(v.z)), v.w - h2f(f2h(v.w)));
            }
        }
        GBAR(bar);

        #pragma unroll 1
        for (int l = 0; l < 4; ++l) {
            const uint32_t rbuf = AG + (uint32_t)(l & 1) * 16384;        // read buf
            const uint32_t wbuf = AG + (uint32_t)((l + 1) & 1) * 16384;  // write buf

            float acc[2][6][4];
            #pragma unroll
            for (int mi = 0; mi < 2; ++mi)
                #pragma unroll
                for (int nt = 0; nt < 6; ++nt)
                    #pragma unroll
                    for (int r = 0; r < 4; ++r) acc[mi][nt][r] = 0.f;

            const uint32_t Babs = sb + WOFF + (uint32_t)l * WLSZ + b_rowoff0;
            #pragma unroll
            for (int ks = 0; ks < 4; ++ks) {
                const uint32_t kb = ks * 32;
                const uint32_t ka = (kb + akadd) ^ aswz;
                const uint32_t kbb = (kb + bkadd) ^ bswz;
                // load-all-then-mma: 7 independent LDSM up front so the next
                // unrolled iteration's loads can hide under this one's 24 mma
                uint32_t b[3][4], a[2][2][4];
                #pragma unroll
                for (int np = 0; np < 3; ++np)
                    LDSM_X4(b[np], Babs + (uint32_t)np * 2048 + kbb);
                #pragma unroll
                for (int s = 0; s < 2; ++s) {
                    const uint32_t Aabs = sb + rbuf + (uint32_t)s * 8192 + a_rowoff;
                    LDSM_X4(a[s][0], Aabs + ka);
                    LDSM_X4(a[s][1], Aabs + 2048 + ka);    // +16 rows, same swizzle
                }
                #pragma unroll
                for (int s = 0; s < 2; ++s)
                    #pragma unroll
                    for (int np = 0; np < 3; ++np) {
                        mma16816(acc[0][2 * np],     a[s][0], b[np][0], b[np][1]);
                        mma16816(acc[0][2 * np + 1], a[s][0], b[np][2], b[np][3]);
                        mma16816(acc[1][2 * np],     a[s][1], b[np][0], b[np][1]);
                        mma16816(acc[1][2 * np + 1], a[s][1], b[np][2], b[np][3]);
                    }
            }

            // register gate epilogue: per mi, frags [3j]=i, [3j+1]=g, [3j+2]=o
            float hreg[2][2][4];
            const float* bl = bs + l * NW + n0 + 2 * tig;
            #pragma unroll
            for (int mi = 0; mi < 2; ++mi) {
                #pragma unroll
                for (int j = 0; j < 2; ++j) {
                    float2 bi = *(const float2*)(bl + j * 24);
                    float2 bg = *(const float2*)(bl + j * 24 + 8);
                    float2 bo = *(const float2*)(bl + j * 24 + 16);
                    const float* ai = acc[mi][3 * j];
                    const float* ag = acc[mi][3 * j + 1];
                    const float* ao = acc[mi][3 * j + 2];
                    hreg[mi][j][0] = hsig(ao[0] + bo.x) * tanh_fast(hsig(ai[0] + bi.x) * tanh_fast(ag[0] + bg.x));
                    hreg[mi][j][1] = hsig(ao[1] + bo.y) * tanh_fast(hsig(ai[1] + bi.y) * tanh_fast(ag[1] + bg.y));
                    hreg[mi][j][2] = hsig(ao[2] + bo.x) * tanh_fast(hsig(ai[2] + bi.x) * tanh_fast(ag[2] + bg.x));
                    hreg[mi][j][3] = hsig(ao[3] + bo.y) * tanh_fast(hsig(ai[3] + bi.y) * tanh_fast(ag[3] + bg.y));
                }
            }

            if (l < 3) {
                // ping-pong: write into wbuf (untouched by this layer's reads)
                #pragma unroll
                for (int mi = 0; mi < 2; ++mi) {
                    const int m1 = mrow + mi * 16 + g8, m2 = m1 + 8;
                    #pragma unroll
                    for (int j = 0; j < 2; ++j) {
                        int c0 = chb + j * 8 + 2 * tig;
                        const float* h = hreg[mi][j];
                        float r00 = h[0] - h2f(f2h(h[0]));
                        float r01 = h[1] - h2f(f2h(h[1]));
                        float r10 = h[2] - h2f(f2h(h[2]));
                        float r11 = h[3] - h2f(f2h(h[3]));
                        uint32_t b1o = (uint32_t)m1 * 128 + (((uint32_t)(2 * c0)) ^ (((uint32_t)m1 & 7) << 4));
                        uint32_t b2o = (uint32_t)m2 * 128 + (((uint32_t)(2 * c0)) ^ (((uint32_t)m2 & 7) << 4));
                        *(uint32_t*)(sm + wbuf + b1o) = pk2hf(h[0], h[1]);
                        *(uint32_t*)(sm + wbuf + 8192 + b1o) = pk2hf(r00, r01);
                        *(uint32_t*)(sm + wbuf + b2o) = pk2hf(h[2], h[3]);
                        *(uint32_t*)(sm + wbuf + 8192 + b2o) = pk2hf(r10, r11);
                    }
                }
                GBAR(bar);   // writes visible before next layer's reads
            } else {
                const size_t p0 = (size_t)t * MTILE;
                #pragma unroll
                for (int mi = 0; mi < 2; ++mi) {
                    const int m1 = mrow + mi * 16 + g8, m2 = m1 + 8;
                    #pragma unroll
                    for (int j = 0; j < 2; ++j) {
                        int c0 = chb + j * 8 + 2 * tig;
                        const float* h = hreg[mi][j];
                        *(float2*)&g_h4[(p0 + m1) * CH + c0] = make_float2(h[0], h[1]);
                        *(float2*)&g_h4[(p0 + m2) * CH + c0] = make_float2(h[2], h[3]);
                    }
                }
            }
        }
    }
}

// ---------------------------------------------------------------------------
// Kernel B: split-K GEMM via fp16 mma, 3-pass (AhBh + AlBh + AhBl ~ fp32-exact):
// partial[g] = flat[:, kb:kb+128] @ D1w[kb:kb+128, :].  M=64(batch) N=64 K=128.
// ---------------------------------------------------------------------------
#define DAH 0
#define DAL 16384
#define DBH 32768
#define DBL 49152
#define SMEM_B_TOT 65536

__global__ void __launch_bounds__(256) k_dense_split(const float* __restrict__ D1w)
{
    extern __shared__ char smf[];
    const uint32_t sb = smem_u32(smf);
    const int tid = threadIdx.x, wid = tid >> 5, lane = tid & 31;
    const size_t kbase = (size_t)blockIdx.x * KC;

    // A: g_h4 [64 b][128 k] fp32 -> hi/lo fp16, rows 256B, XOR swz
    #pragma unroll
    for (int i = 0; i < 8; ++i) {
        int fi = tid + i * 256;                 // 2048 float4
        int b = fi >> 5, kq = fi & 31;          // k = kq*4
        float4 v = *(const float4*)(g_h4 + (size_t)b * FLATK + kbase + (size_t)kq * 4);
        uint32_t off = (uint32_t)b * 256 + (((uint32_t)(kq * 8)) ^ (((uint32_t)b & 7) << 4));
        *(u64*)(smf + DAH + off) = pack4hf(v.x, v.y, v.z, v.w);
        *(u64*)(smf + DAL + off) = pack4hf(
            v.x - h2f(f2h(v.x)), v.y - h2f(f2h(v.y)),
            v.z - h2f(f2h(v.z)), v.w - h2f(f2h(v.w)));
    }
    // B: D1w [128 k][64 n] fp32 -> transpose to [64 n][128 k] hi/lo fp16
    #pragma unroll
    for (int i = 0; i < 8; ++i) {
        int fi = tid + i * 256;                 // 2048 float4
        int k = fi >> 4, n4 = (fi & 15) << 2;
        float4 v = ((const float4*)(D1w + (kbase + k) * 64))[fi & 15];
        float vv[4] = {v.x, v.y, v.z, v.w};
        #pragma unroll
        for (int e = 0; e < 4; ++e) {
            int n = n4 + e;
            uint32_t off = (uint32_t)n * 256 + (((uint32_t)(2 * k)) ^ (((uint32_t)n & 7) << 4));
            unsigned short hh = f2h(vv[e]);
            *(unsigned short*)(smf + DBH + off) = hh;
            *(unsigned short*)(smf + DBL + off) = f2h(vv[e] - h2f(hh));
        }
    }
    __syncthreads();

    // 8 warps: mw 0..3 (16 batch rows), nw 0..1 (32 n cols)
    const int mw = wid & 3, nw = wid >> 2;
    const int lt = lane >> 3, lr = lane & 7;
    const int g8 = lane >> 2, tig = lane & 3;
    const int arow = mw * 16 + ((lt & 1) << 3) + lr;
    const uint32_t a_ro = (uint32_t)arow * 256, aswz = ((uint32_t)arow & 7) << 4;
    const int akadd = (lt >> 1) << 4;
    const int brow = nw * 32 + ((lt >> 1) << 3) + lr;
    const uint32_t b_ro = (uint32_t)brow * 256, bswz = ((uint32_t)brow & 7) << 4;
    const int bkadd = (lt & 1) << 4;

    float acc[4][4];
    #pragma unroll
    for (int nf = 0; nf < 4; ++nf)
        #pragma unroll
        for (int r = 0; r < 4; ++r) acc[nf][r] = 0.f;

    #pragma unroll
    for (int ks = 0; ks < 8; ++ks) {
        const uint32_t kb = ks * 32;
        const uint32_t ka = (kb + akadd) ^ aswz;
        const uint32_t kbb = (kb + bkadd) ^ bswz;
        uint32_t ah[4], al[4], bh0[4], bh1[4], bl0[4], bl1[4];
        LDSM_X4(ah, sb + DAH + a_ro + ka);
        LDSM_X4(al, sb + DAL + a_ro + ka);
        LDSM_X4(bh0, sb + DBH + b_ro + kbb);
        LDSM_X4(bh1, sb + DBH + b_ro + 4096 + kbb);   // +16 n rows
        LDSM_X4(bl0, sb + DBL + b_ro + kbb);
        LDSM_X4(bl1, sb + DBL + b_ro + 4096 + kbb);
        mma16816(acc[0], ah, bh0[0], bh0[1]);
        mma16816(acc[1], ah, bh0[2], bh0[3]);
        mma16816(acc[2], ah, bh1[0], bh1[1]);
        mma16816(acc[3], ah, bh1[2], bh1[3]);
        mma16816(acc[0], al, bh0[0], bh0[1]);
        mma16816(acc[1], al, bh0[2], bh0[3]);
        mma16816(acc[2], al, bh1[0], bh1[1]);
        mma16816(acc[3], al, bh1[2], bh1[3]);
        mma16816(acc[0], ah, bl0[0], bl0[1]);
        mma16816(acc[1], ah, bl0[2], bl0[3]);
        mma16816(acc[2], ah, bl1[0], bl1[1]);
        mma16816(acc[3], ah, bl1[2], bl1[3]);
    }

    float* dst = g_part + (size_t)blockIdx.x * 4096;
    const int m1 = mw * 16 + g8, m2 = m1 + 8;
    #pragma unroll
    for (int nf = 0; nf < 4; ++nf) {
        int n = nw * 32 + nf * 8 + 2 * tig;
        *(float2*)&dst[m1 * 64 + n] = make_float2(acc[nf][0], acc[nf][1]);
        *(float2*)&dst[m2 * 64 + n] = make_float2(acc[nf][2], acc[nf][3]);
    }
}

// ---------------------------------------------------------------------------
// Kernel C1: stage-1 reduce: 2048 blocks, each sums 32 g-slices for (b,chunk).
// ---------------------------------------------------------------------------
__global__ void k_red1()
{
    __shared__ float sred[256];
    const int blk = blockIdx.x;            // 2048 = 64 b x 32 chunks
    const int b = blk >> 5, chunk = blk & 31;
    const int tid = threadIdx.x;
    const int n = tid & 63, sub = tid >> 6;
    const float* p = g_part + (size_t)(chunk * 32 + sub * 8) * 4096 + (size_t)b * 64 + n;
    float s = 0.f;
    #pragma unroll
    for (int t = 0; t < 8; ++t) s += p[(size_t)t * 4096];
    sred[tid] = s;
    __syncthreads();
    if (tid < 64)
        g_red[chunk * 4096 + b * 64 + n] =
            sred[tid] + sred[tid + 64] + sred[tid + 128] + sred[tid + 192];
}

// ---------------------------------------------------------------------------
// Kernel C2: final: sum 32 chunks + D1b + relu + D2 GEMV. 64 blocks x 64 thr.
// ---------------------------------------------------------------------------
__global__ void k_final(const float* __restrict__ D1b, const float* __restrict__ D2w,
                        const float* __restrict__ D2b, float* __restrict__ out)
{
    __shared__ float sA[2];
    const int b = blockIdx.x, n = threadIdx.x;   // 64 threads
    float v = 0.f;
    #pragma unroll
    for (int ch = 0; ch < RCH; ++ch) v += g_red[ch * 4096 + b * 64 + n];
    float y = fmaxf(v + D1b[n], 0.f) * D2w[n];
    #pragma unroll
    for (int off = 16; off > 0; off >>= 1)
        y += __shfl_down_sync(0xffffffffu, y, off);
    if ((n & 31) == 0) sA[n >> 5] = y;
    __syncthreads();
    if (n == 0) out[b] = sA[0] + sA[1] + D2b[0];
}

// ---------------------------------------------------------------------------
extern "C" void kernel_launch(void* const* d_in, const int* in_sizes, int n_in,
                              void* d_out, int out_size)
{
    const float* x   = (const float*)d_in[0];
    const float* W1x = (const float*)d_in[1];
    const float* b1  = (const float*)d_in[3];
    const float* W2x = (const float*)d_in[4];
    const float* b2  = (const float*)d_in[6];
    const float* W3x = (const float*)d_in[7];
    const float* b3  = (const float*)d_in[9];
    const float* W4x = (const float*)d_in[10];
    const float* b4  = (const float*)d_in[12];
    const float* D1w = (const float*)d_in[13];
    const float* D1b = (const float*)d_in[14];
    const float* D2w = (const float*)d_in[15];
    const float* D2b = (const float*)d_in[16];

    cudaFuncSetAttribute(k_lstm4, cudaFuncAttributeMaxDynamicSharedMemorySize, SMEM_A_TOT);
    cudaFuncSetAttribute(k_dense_split, cudaFuncAttributeMaxDynamicSharedMemorySize, SMEM_B_TOT);

    // SAME padding over H=1 picks exactly one kernel row: r=4 (kh=10), r=2 (kh=5)
    k_prep<<<4, 256>>>(W1x + 4 * 64 * 256, W2x + 2 * 64 * 256,
                       W3x + 4 * 64 * 256, W4x + 2 * 64 * 256,
                       b1, b2, b3, b4);
    k_lstm4<<<GRID_A, THR_A, SMEM_A_TOT>>>(x);
    k_dense_split<<<GSPLIT, 256, SMEM_B_TOT>>>(D1w);
    k_red1<<<2048, 256>>>();
    k_final<<<BATCH, 64>>>(D1b, D2w, D2b, (float*)d_out);
}

// round 16
// speedup vs baseline: 1.1882x; 1.0859x over previous
#include <cuda_runtime.h>
#include <cuda_fp16.h>
#include <cstdint>
#include <math.h>

#define BATCH 64
#define WPOS  2048
#define NPOS  (BATCH * WPOS)      // 131072 positions
#define CH    64
#define MTILE 64                  // positions per tile (kernel A)
#define NTILES (NPOS / MTILE)     // 2048
#define GRID_A 148                // persistent blocks (1/SM)
#define THR_A  512                // 2 groups x 256
#define KC    128                 // K chunk for dense split-K
#define FLATK (WPOS * CH)         // 131072
#define GSPLIT (FLATK / KC)       // 1024
#define NW    192                 // gates i,g,o (f gate dead)
#define RCH   32                  // red1 chunks

// ---- scratch (device globals; no allocation allowed) -----------------------
__device__ __align__(16) float g_h4[(size_t)NPOS * CH];            // 32 MB
__device__ __align__(16) float g_part[(size_t)GSPLIT * 64 * 64];   // 16 MB
__device__ __align__(16) float g_red[RCH * 64 * 64];               // 512 KB
__device__ __align__(16) unsigned short g_Wh[4][NW * 64];          // pre-swizzled fp16 weights
__device__ __align__(16) float g_Bp[4][NW];

typedef unsigned long long u64;

__device__ __forceinline__ float hsig(float v) {
    return __saturatef(fmaf(v, 0.2f, 0.5f));
}
__device__ __forceinline__ float tanh_fast(float v) {   // MUFU.TANH, sm_75+
    float r; asm("tanh.approx.f32 %0,%1;" : "=f"(r) : "f"(v)); return r;
}
__device__ __forceinline__ uint32_t smem_u32(const void* p) {
    uint32_t a;
    asm("{ .reg .u64 t; cvta.to.shared.u64 t, %1; cvt.u32.u64 %0, t; }" : "=r"(a) : "l"(p));
    return a;
}
#define GBAR(id) asm volatile("bar.sync %0, 256;" :: "r"(id) : "memory")

// warp-level fp16 mma + ldmatrix (plain sm_80+ PTX; tcgen05 is 'a'-gated)
__device__ __forceinline__ void mma16816(float* c, const uint32_t* a, uint32_t b0, uint32_t b1) {
    asm volatile(
        "mma.sync.aligned.m16n8k16.row.col.f32.f16.f16.f32 "
        "{%0,%1,%2,%3},{%4,%5,%6,%7},{%8,%9},{%0,%1,%2,%3};"
        : "+f"(c[0]), "+f"(c[1]), "+f"(c[2]), "+f"(c[3])
        : "r"(a[0]), "r"(a[1]), "r"(a[2]), "r"(a[3]), "r"(b0), "r"(b1));
}
#define LDSM_X4(r, a) \
    asm volatile("ldmatrix.sync.aligned.m8n8.x4.shared.b16 {%0,%1,%2,%3}, [%4];" \
        : "=r"((r)[0]), "=r"((r)[1]), "=r"((r)[2]), "=r"((r)[3]) : "r"(a))
#define LDSM_X4T(r, a) \
    asm volatile("ldmatrix.sync.aligned.m8n8.x4.trans.shared.b16 {%0,%1,%2,%3}, [%4];" \
        : "=r"((r)[0]), "=r"((r)[1]), "=r"((r)[2]), "=r"((r)[3]) : "r"(a))

__device__ __forceinline__ unsigned short f2h(float a) {
    return __half_as_ushort(__float2half_rn(a));
}
__device__ __forceinline__ float h2f(unsigned short a) {
    return __half2float(__ushort_as_half(a));
}
__device__ __forceinline__ u64 pack4hf(float a, float b, float c, float d) {
    return (u64)f2h(a) | ((u64)f2h(b) << 16) | ((u64)f2h(c) << 32) | ((u64)f2h(d) << 48);
}
__device__ __forceinline__ uint32_t pk2hf(float a, float b) {
    return (uint32_t)f2h(a) | ((uint32_t)f2h(b) << 16);
}

// lstm4 smem layout (bytes): 4 fp16 weight images + 2 groups x 2 ping-pong A bufs + bias
#define WOFF   0                        // 4 x 24576 fp16 [192n][64k] XOR-swz
#define WLSZ   24576
#define ABUF   (4 * WLSZ)               // 98304: grp stride 32768, buf stride 16384
#define BIAS   (ABUF + 65536)           // 163840: 4*192 f32
#define SMEM_A_TOT 166912

// ---------------------------------------------------------------------------
// Prep: fp16 weight slices, GATE-INTERLEAVED n-order for 48-col n-quarters:
//   n = q*48 + j*24 + gate*8 + e  ->  channel c = q*16 + j*8 + e
// XOR row swizzle pre-applied so blocks copy verbatim.
// ---------------------------------------------------------------------------
__global__ void k_prep(const float* __restrict__ W0, const float* __restrict__ W1,
                       const float* __restrict__ W2, const float* __restrict__ W3,
                       const float* __restrict__ B0, const float* __restrict__ B1,
                       const float* __restrict__ B2, const float* __restrict__ B3)
{
    const int l = blockIdx.x, tid = threadIdx.x;
    const float* W  = (l == 0) ? W0 : (l == 1) ? W1 : (l == 2) ? W2 : W3;
    const float* Bb = (l == 0) ? B0 : (l == 1) ? B1 : (l == 2) ? B2 : B3;
    for (int idx = tid; idx < NW * 64; idx += 256) {
        int n = idx >> 6, k = idx & 63;
        int q = n / 48, r = n % 48;
        int j = r / 24, gate = (r % 24) >> 3, e = r & 7;
        int c = q * 16 + j * 8 + e;
        int gn = (gate == 0) ? c : (gate == 1) ? 128 + c : 192 + c;   // skip dead f gate
        uint32_t sw = (uint32_t)n * 64 + ((((uint32_t)(2 * k)) ^ (((uint32_t)n & 7) << 4)) >> 1);
        g_Wh[l][sw] = f2h(W[k * 256 + gn]);
    }
    for (int n = tid; n < NW; n += 256) {
        int q = n / 48, r = n % 48;
        int j = r / 24, gate = (r % 24) >> 3, e = r & 7;
        int c = q * 16 + j * 8 + e;
        int gn = (gate == 0) ? c : (gate == 1) ? 128 + c : 192 + c;
        g_Bp[l][n] = Bb[gn];
    }
}

// ---------------------------------------------------------------------------
// Kernel A: persistent fused 4x ConvLSTM via mma.sync fp16 2-pass.
// (unchanged from best: 82us, at legacy-HMMA rate)
// ---------------------------------------------------------------------------
__global__ void __launch_bounds__(THR_A, 1) k_lstm4(const float* __restrict__ x)
{
    extern __shared__ char sm[];
    const uint32_t sb = smem_u32(sm);
    const int tid = threadIdx.x;
    const int wid = tid >> 5, lane = tid & 31;
    const int grp = tid >> 8;            // barrier group 0/1
    const int tig256 = tid & 255;        // tid within group
    const int g8 = lane >> 2, tig = lane & 3;

    // one-time: weights (96KB) + biases -> smem (all 512 threads)
    {
        const uint4* src = (const uint4*)g_Wh;
        uint4* dst = (uint4*)(sm + WOFF);
        #pragma unroll
        for (int i = 0; i < 12; ++i) dst[tid + i * THR_A] = src[tid + i * THR_A];
        float* bsw = (float*)(sm + BIAS);
        #pragma unroll
        for (int i = 0; i < 2; ++i) {
            int idx = tid + i * THR_A;
            if (idx < 4 * NW) bsw[idx] = ((const float*)g_Bp)[idx];
        }
    }
    __syncthreads();                     // weights immutable hereafter
    const float* bs = (const float*)(sm + BIAS);

    // group-local warp layout: 8 warps = 2 m-groups (32 rows) x 4 n-quarters (48 cols)
    const int wg = wid & 7;
    const int lt = lane >> 3, lr = lane & 7;
    const int mgrp = wg & 1, nq = wg >> 1;
    const int mrow = mgrp * 32, n0 = nq * 48, chb = nq * 16;
    const uint32_t AG = ABUF + (uint32_t)grp * 32768;   // group's buffer base
    const int arow = mrow + ((lt & 1) << 3) + lr;
    const uint32_t a_rowoff = (uint32_t)arow * 128;
    const uint32_t aswz = ((uint32_t)arow & 7) << 4;
    const int akadd = (lt >> 1) << 4;
    const int brow0 = n0 + ((lt >> 1) << 3) + lr;
    const uint32_t b_rowoff0 = (uint32_t)brow0 * 128;
    const uint32_t bswz = ((uint32_t)brow0 & 7) << 4;
    const int bkadd = (lt & 1) << 4;
    const int bar = grp + 1;

    for (int t = blockIdx.x * 2 + grp; t < NTILES; t += GRID_A * 2) {
        // stage input tile into buf0 (hi at +0, lo at +8192); overlaps prev L3
        {
            const float4* xin = (const float4*)(x + (size_t)t * MTILE * CH);
            #pragma unroll
            for (int i = 0; i < 4; ++i) {
                int fi = tig256 + i * 256;          // 1024 float4
                int pos = fi >> 4, c = (fi & 15) << 2;
                float4 v = xin[fi];
                uint32_t b = (uint32_t)pos * 128 + (((uint32_t)(2 * c)) ^ (((uint32_t)pos & 7) << 4));
                *(u64*)(sm + AG + b) = pack4hf(v.x, v.y, v.z, v.w);
                *(u64*)(sm + AG + 8192 + b) = pack4hf(
                    v.x - h2f(f2h(v.x)), v.y - h2f(f2h(v.y)),
                    v.z - h2f(f2h(v.z)), v.w - h2f(f2h(v.w)));
            }
        }
        GBAR(bar);

        #pragma unroll 1
        for (int l = 0; l < 4; ++l) {
            const uint32_t rbuf = AG + (uint32_t)(l & 1) * 16384;        // read buf
            const uint32_t wbuf = AG + (uint32_t)((l + 1) & 1) * 16384;  // write buf

            float acc[2][6][4];
            #pragma unroll
            for (int mi = 0; mi < 2; ++mi)
                #pragma unroll
                for (int nt = 0; nt < 6; ++nt)
                    #pragma unroll
                    for (int r = 0; r < 4; ++r) acc[mi][nt][r] = 0.f;

            const uint32_t Babs = sb + WOFF + (uint32_t)l * WLSZ + b_rowoff0;
            #pragma unroll
            for (int ks = 0; ks < 4; ++ks) {
                const uint32_t kb = ks * 32;
                const uint32_t ka = (kb + akadd) ^ aswz;
                const uint32_t kbb = (kb + bkadd) ^ bswz;
                uint32_t b[3][4], a[2][2][4];
                #pragma unroll
                for (int np = 0; np < 3; ++np)
                    LDSM_X4(b[np], Babs + (uint32_t)np * 2048 + kbb);
                #pragma unroll
                for (int s = 0; s < 2; ++s) {
                    const uint32_t Aabs = sb + rbuf + (uint32_t)s * 8192 + a_rowoff;
                    LDSM_X4(a[s][0], Aabs + ka);
                    LDSM_X4(a[s][1], Aabs + 2048 + ka);    // +16 rows, same swizzle
                }
                #pragma unroll
                for (int s = 0; s < 2; ++s)
                    #pragma unroll
                    for (int np = 0; np < 3; ++np) {
                        mma16816(acc[0][2 * np],     a[s][0], b[np][0], b[np][1]);
                        mma16816(acc[0][2 * np + 1], a[s][0], b[np][2], b[np][3]);
                        mma16816(acc[1][2 * np],     a[s][1], b[np][0], b[np][1]);
                        mma16816(acc[1][2 * np + 1], a[s][1], b[np][2], b[np][3]);
                    }
            }

            // register gate epilogue: per mi, frags [3j]=i, [3j+1]=g, [3j+2]=o
            float hreg[2][2][4];
            const float* bl = bs + l * NW + n0 + 2 * tig;
            #pragma unroll
            for (int mi = 0; mi < 2; ++mi) {
                #pragma unroll
                for (int j = 0; j < 2; ++j) {
                    float2 bi = *(const float2*)(bl + j * 24);
                    float2 bg = *(const float2*)(bl + j * 24 + 8);
                    float2 bo = *(const float2*)(bl + j * 24 + 16);
                    const float* ai = acc[mi][3 * j];
                    const float* ag = acc[mi][3 * j + 1];
                    const float* ao = acc[mi][3 * j + 2];
                    hreg[mi][j][0] = hsig(ao[0] + bo.x) * tanh_fast(hsig(ai[0] + bi.x) * tanh_fast(ag[0] + bg.x));
                    hreg[mi][j][1] = hsig(ao[1] + bo.y) * tanh_fast(hsig(ai[1] + bi.y) * tanh_fast(ag[1] + bg.y));
                    hreg[mi][j][2] = hsig(ao[2] + bo.x) * tanh_fast(hsig(ai[2] + bi.x) * tanh_fast(ag[2] + bg.x));
                    hreg[mi][j][3] = hsig(ao[3] + bo.y) * tanh_fast(hsig(ai[3] + bi.y) * tanh_fast(ag[3] + bg.y));
                }
            }

            if (l < 3) {
                // ping-pong: write into wbuf (untouched by this layer's reads)
                #pragma unroll
                for (int mi = 0; mi < 2; ++mi) {
                    const int m1 = mrow + mi * 16 + g8, m2 = m1 + 8;
                    #pragma unroll
                    for (int j = 0; j < 2; ++j) {
                        int c0 = chb + j * 8 + 2 * tig;
                        const float* h = hreg[mi][j];
                        float r00 = h[0] - h2f(f2h(h[0]));
                        float r01 = h[1] - h2f(f2h(h[1]));
                        float r10 = h[2] - h2f(f2h(h[2]));
                        float r11 = h[3] - h2f(f2h(h[3]));
                        uint32_t b1o = (uint32_t)m1 * 128 + (((uint32_t)(2 * c0)) ^ (((uint32_t)m1 & 7) << 4));
                        uint32_t b2o = (uint32_t)m2 * 128 + (((uint32_t)(2 * c0)) ^ (((uint32_t)m2 & 7) << 4));
                        *(uint32_t*)(sm + wbuf + b1o) = pk2hf(h[0], h[1]);
                        *(uint32_t*)(sm + wbuf + 8192 + b1o) = pk2hf(r00, r01);
                        *(uint32_t*)(sm + wbuf + b2o) = pk2hf(h[2], h[3]);
                        *(uint32_t*)(sm + wbuf + 8192 + b2o) = pk2hf(r10, r11);
                    }
                }
                GBAR(bar);   // writes visible before next layer's reads
            } else {
                const size_t p0 = (size_t)t * MTILE;
                #pragma unroll
                for (int mi = 0; mi < 2; ++mi) {
                    const int m1 = mrow + mi * 16 + g8, m2 = m1 + 8;
                    #pragma unroll
                    for (int j = 0; j < 2; ++j) {
                        int c0 = chb + j * 8 + 2 * tig;
                        const float* h = hreg[mi][j];
                        *(float2*)&g_h4[(p0 + m1) * CH + c0] = make_float2(h[0], h[1]);
                        *(float2*)&g_h4[(p0 + m2) * CH + c0] = make_float2(h[2], h[3]);
                    }
                }
            }
        }
    }
}

// ---------------------------------------------------------------------------
// Kernel B: split-K GEMM via fp16 mma, 3-pass (AhBh + AlBh + AhBl ~ fp32-exact):
// partial[g] = flat[:, kb:kb+128] @ D1w[kb:kb+128, :].  M=64(batch) N=64 K=128.
// B stored NATURAL row-major [128k][64n] (coalesced conflict-free staging —
// the old transpose-at-store hit 32-way bank conflicts); col-major fragments
// fetched via ldmatrix.x4.trans.
// ---------------------------------------------------------------------------
#define DAH 0
#define DAL 16384
#define DBH 32768
#define DBL 49152
#define SMEM_B_TOT 65536

__global__ void __launch_bounds__(256) k_dense_split(const float* __restrict__ D1w)
{
    extern __shared__ char smf[];
    const uint32_t sb = smem_u32(smf);
    const int tid = threadIdx.x, wid = tid >> 5, lane = tid & 31;
    const size_t kbase = (size_t)blockIdx.x * KC;

    // A: g_h4 [64 b][128 k] fp32 -> hi/lo fp16, rows 256B, XOR swz (unchanged)
    #pragma unroll
    for (int i = 0; i < 8; ++i) {
        int fi = tid + i * 256;                 // 2048 float4
        int b = fi >> 5, kq = fi & 31;          // k = kq*4
        float4 v = *(const float4*)(g_h4 + (size_t)b * FLATK + kbase + (size_t)kq * 4);
        uint32_t off = (uint32_t)b * 256 + (((uint32_t)(kq * 8)) ^ (((uint32_t)b & 7) << 4));
        *(u64*)(smf + DAH + off) = pack4hf(v.x, v.y, v.z, v.w);
        *(u64*)(smf + DAL + off) = pack4hf(
            v.x - h2f(f2h(v.x)), v.y - h2f(f2h(v.y)),
            v.z - h2f(f2h(v.z)), v.w - h2f(f2h(v.w)));
    }
    // B: D1w [128 k][64 n] fp32 -> fp16 hi/lo kept ROW-MAJOR [k][n], rows 128B,
    // XOR swz on 16B units; contiguous u64 stores (no transpose, no conflicts)
    #pragma unroll
    for (int i = 0; i < 8; ++i) {
        int fi = tid + i * 256;                 // 2048 float4
        int k = fi >> 4, nq = fi & 15;          // n = nq*4
        float4 v = ((const float4*)(D1w + (kbase + k) * 64))[nq];
        uint32_t off = (uint32_t)k * 128 + (((uint32_t)(nq * 8)) ^ (((uint32_t)k & 7) << 4));
        *(u64*)(smf + DBH + off) = pack4hf(v.x, v.y, v.z, v.w);
        *(u64*)(smf + DBL + off) = pack4hf(
            v.x - h2f(f2h(v.x)), v.y - h2f(f2h(v.y)),
            v.z - h2f(f2h(v.z)), v.w - h2f(f2h(v.w)));
    }
    __syncthreads();

    // 8 warps: mw 0..3 (16 batch rows), nw 0..1 (32 n cols)
    const int mw = wid & 3, nw = wid >> 2;
    const int lt = lane >> 3, lr = lane & 7;
    const int g8 = lane >> 2, tig = lane & 3;
    const int arow = mw * 16 + ((lt & 1) << 3) + lr;
    const uint32_t a_ro = (uint32_t)arow * 256, aswz = ((uint32_t)arow & 7) << 4;
    const int akadd = (lt >> 1) << 4;
    // B trans-ldmatrix lane roles: row k = ks*16 + (lt&1)*8 + lr, n group (lt>>1)*8
    const uint32_t b_row = (uint32_t)(((lt & 1) << 3) + lr) * 128;  // within-ks row offset
    const uint32_t bksw = ((uint32_t)lr) << 4;                      // (k&7)<<4
    const uint32_t bn0 = (uint32_t)(nw * 64) + ((uint32_t)(lt >> 1) << 4);  // byte offset of n

    float acc[4][4];
    #pragma unroll
    for (int nf = 0; nf < 4; ++nf)
        #pragma unroll
        for (int r = 0; r < 4; ++r) acc[nf][r] = 0.f;

    #pragma unroll
    for (int ks = 0; ks < 8; ++ks) {
        const uint32_t kb = ks * 32;
        const uint32_t ka = (kb + akadd) ^ aswz;
        const uint32_t bko = (uint32_t)ks * 2048 + b_row;   // k-row byte offset
        uint32_t ah[4], al[4], bh0[4], bh1[4], bl0[4], bl1[4];
        LDSM_X4(ah, sb + DAH + a_ro + ka);
        LDSM_X4(al, sb + DAL + a_ro + ka);
        LDSM_X4T(bh0, sb + DBH + bko + (bn0 ^ bksw));
        LDSM_X4T(bh1, sb + DBH + bko + ((bn0 + 32) ^ bksw));   // +16 n
        LDSM_X4T(bl0, sb + DBL + bko + (bn0 ^ bksw));
        LDSM_X4T(bl1, sb + DBL + bko + ((bn0 + 32) ^ bksw));
        mma16816(acc[0], ah, bh0[0], bh0[1]);
        mma16816(acc[1], ah, bh0[2], bh0[3]);
        mma16816(acc[2], ah, bh1[0], bh1[1]);
        mma16816(acc[3], ah, bh1[2], bh1[3]);
        mma16816(acc[0], al, bh0[0], bh0[1]);
        mma16816(acc[1], al, bh0[2], bh0[3]);
        mma16816(acc[2], al, bh1[0], bh1[1]);
        mma16816(acc[3], al, bh1[2], bh1[3]);
        mma16816(acc[0], ah, bl0[0], bl0[1]);
        mma16816(acc[1], ah, bl0[2], bl0[3]);
        mma16816(acc[2], ah, bl1[0], bl1[1]);
        mma16816(acc[3], ah, bl1[2], bl1[3]);
    }

    float* dst = g_part + (size_t)blockIdx.x * 4096;
    const int m1 = mw * 16 + g8, m2 = m1 + 8;
    #pragma unroll
    for (int nf = 0; nf < 4; ++nf) {
        int n = nw * 32 + nf * 8 + 2 * tig;
        *(float2*)&dst[m1 * 64 + n] = make_float2(acc[nf][0], acc[nf][1]);
        *(float2*)&dst[m2 * 64 + n] = make_float2(acc[nf][2], acc[nf][3]);
    }
}

// ---------------------------------------------------------------------------
// Kernel C1: stage-1 reduce: 2048 blocks, each sums 32 g-slices for (b,chunk).
// ---------------------------------------------------------------------------
__global__ void k_red1()
{
    __shared__ float sred[256];
    const int blk = blockIdx.x;            // 2048 = 64 b x 32 chunks
    const int b = blk >> 5, chunk = blk & 31;
    const int tid = threadIdx.x;
    const int n = tid & 63, sub = tid >> 6;
    const float* p = g_part + (size_t)(chunk * 32 + sub * 8) * 4096 + (size_t)b * 64 + n;
    float s = 0.f;
    #pragma unroll
    for (int t = 0; t < 8; ++t) s += p[(size_t)t * 4096];
    sred[tid] = s;
    __syncthreads();
    if (tid < 64)
        g_red[chunk * 4096 + b * 64 + n] =
            sred[tid] + sred[tid + 64] + sred[tid + 128] + sred[tid + 192];
}

// ---------------------------------------------------------------------------
// Kernel C2: final: sum 32 chunks + D1b + relu + D2 GEMV. 64 blocks x 64 thr.
// ---------------------------------------------------------------------------
__global__ void k_final(const float* __restrict__ D1b, const float* __restrict__ D2w,
                        const float* __restrict__ D2b, float* __restrict__ out)
{
    __shared__ float sA[2];
    const int b = blockIdx.x, n = threadIdx.x;   // 64 threads
    float v = 0.f;
    #pragma unroll
    for (int ch = 0; ch < RCH; ++ch) v += g_red[ch * 4096 + b * 64 + n];
    float y = fmaxf(v + D1b[n], 0.f) * D2w[n];
    #pragma unroll
    for (int off = 16; off > 0; off >>= 1)
        y += __shfl_down_sync(0xffffffffu, y, off);
    if ((n & 31) == 0) sA[n >> 5] = y;
    __syncthreads();
    if (n == 0) out[b] = sA[0] + sA[1] + D2b[0];
}

// ---------------------------------------------------------------------------
extern "C" void kernel_launch(void* const* d_in, const int* in_sizes, int n_in,
                              void* d_out, int out_size)
{
    const float* x   = (const float*)d_in[0];
    const float* W1x = (const float*)d_in[1];
    const float* b1  = (const float*)d_in[3];
    const float* W2x = (const float*)d_in[4];
    const float* b2  = (const float*)d_in[6];
    const float* W3x = (const float*)d_in[7];
    const float* b3  = (const float*)d_in[9];
    const float* W4x = (const float*)d_in[10];
    const float* b4  = (const float*)d_in[12];
    const float* D1w = (const float*)d_in[13];
    const float* D1b = (const float*)d_in[14];
    const float* D2w = (const float*)d_in[15];
    const float* D2b = (const float*)d_in[16];

    cudaFuncSetAttribute(k_lstm4, cudaFuncAttributeMaxDynamicSharedMemorySize, SMEM_A_TOT);
    cudaFuncSetAttribute(k_dense_split, cudaFuncAttributeMaxDynamicSharedMemorySize, SMEM_B_TOT);

    // SAME padding over H=1 picks exactly one kernel row: r=4 (kh=10), r=2 (kh=5)
    k_prep<<<4, 256>>>(W1x + 4 * 64 * 256, W2x + 2 * 64 * 256,
                       W3x + 4 * 64 * 256, W4x + 2 * 64 * 256,
                       b1, b2, b3, b4);
    k_lstm4<<<GRID_A, THR_A, SMEM_A_TOT>>>(x);
    k_dense_split<<<GSPLIT, 256, SMEM_B_TOT>>>(D1w);
    k_red1<<<2048, 256>>>();
    k_final<<<BATCH, 64>>>(D1b, D2w, D2b, (float*)d_out);
}

// round 17
// speedup vs baseline: 1.5270x; 1.2852x over previous
#include <cuda_runtime.h>
#include <cuda_fp16.h>
#include <cstdint>
#include <math.h>

#define BATCH 64
#define WPOS  2048
#define NPOS  (BATCH * WPOS)      // 131072 positions
#define CH    64
#define MTILE 64                  // positions per tile (kernel A)
#define NTILES (NPOS / MTILE)     // 2048
#define GRID_A 148                // persistent blocks (1/SM)
#define THR_A  512                // 2 groups x 256
#define KC    128                 // K chunk for dense split-K
#define FLATK (WPOS * CH)         // 131072
#define GSPLIT (FLATK / KC)       // 1024
#define NW    192                 // gates i,g,o (f gate dead)
#define RCH   32                  // red1 chunks

// ---- scratch (device globals; no allocation allowed) -----------------------
__device__ __align__(16) float g_h4[(size_t)NPOS * CH];            // 32 MB
__device__ __align__(16) float g_part[(size_t)GSPLIT * 64 * 64];   // 16 MB
__device__ __align__(16) float g_red[RCH * 64 * 64];               // 512 KB
__device__ __align__(16) unsigned short g_Wh[4][NW * 64];          // pre-swizzled fp16 weights
__device__ __align__(16) float g_Bp[4][NW];

typedef unsigned long long u64;

__device__ __forceinline__ float hsig(float v) {
    return __saturatef(fmaf(v, 0.2f, 0.5f));
}
__device__ __forceinline__ float tanh_fast(float v) {   // MUFU.TANH, sm_75+
    float r; asm("tanh.approx.f32 %0,%1;" : "=f"(r) : "f"(v)); return r;
}
__device__ __forceinline__ uint32_t smem_u32(const void* p) {
    uint32_t a;
    asm("{ .reg .u64 t; cvta.to.shared.u64 t, %1; cvt.u32.u64 %0, t; }" : "=r"(a) : "l"(p));
    return a;
}
#define GBAR(id) asm volatile("bar.sync %0, 256;" :: "r"(id) : "memory")

// warp-level fp16 mma + ldmatrix (plain sm_80+ PTX; tcgen05 is 'a'-gated)
__device__ __forceinline__ void mma16816(float* c, const uint32_t* a, uint32_t b0, uint32_t b1) {
    asm volatile(
        "mma.sync.aligned.m16n8k16.row.col.f32.f16.f16.f32 "
        "{%0,%1,%2,%3},{%4,%5,%6,%7},{%8,%9},{%0,%1,%2,%3};"
        : "+f"(c[0]), "+f"(c[1]), "+f"(c[2]), "+f"(c[3])
        : "r"(a[0]), "r"(a[1]), "r"(a[2]), "r"(a[3]), "r"(b0), "r"(b1));
}
#define LDSM_X4(r, a) \
    asm volatile("ldmatrix.sync.aligned.m8n8.x4.shared.b16 {%0,%1,%2,%3}, [%4];" \
        : "=r"((r)[0]), "=r"((r)[1]), "=r"((r)[2]), "=r"((r)[3]) : "r"(a))
#define LDSM_X4T(r, a) \
    asm volatile("ldmatrix.sync.aligned.m8n8.x4.trans.shared.b16 {%0,%1,%2,%3}, [%4];" \
        : "=r"((r)[0]), "=r"((r)[1]), "=r"((r)[2]), "=r"((r)[3]) : "r"(a))

__device__ __forceinline__ unsigned short f2h(float a) {
    return __half_as_ushort(__float2half_rn(a));
}
__device__ __forceinline__ float h2f(unsigned short a) {
    return __half2float(__ushort_as_half(a));
}
__device__ __forceinline__ u64 pack4hf(float a, float b, float c, float d) {
    return (u64)f2h(a) | ((u64)f2h(b) << 16) | ((u64)f2h(c) << 32) | ((u64)f2h(d) << 48);
}
__device__ __forceinline__ uint32_t pk2hf(float a, float b) {
    return (uint32_t)f2h(a) | ((uint32_t)f2h(b) << 16);
}

// lstm4 smem (bytes): 4 fp16 weight images + 2 groups x 2 ping-pong A bufs + bias
#define WOFF   0                        // 4 x 24576 fp16 [192n][64k] XOR-swz
#define WLSZ   24576
#define ABUF   (4 * WLSZ)               // 98304: grp stride 16384, buf stride 8192
#define BIAS   (ABUF + 32768)           // 131072: 4*192 f32
#define SMEM_A_TOT 134144

// ---------------------------------------------------------------------------
// Prep: fp16 weight slices, GATE-INTERLEAVED n-order for 48-col n-quarters:
//   n = q*48 + j*24 + gate*8 + e  ->  channel c = q*16 + j*8 + e
// XOR row swizzle pre-applied so blocks copy verbatim.
// ---------------------------------------------------------------------------
__global__ void k_prep(const float* __restrict__ W0, const float* __restrict__ W1,
                       const float* __restrict__ W2, const float* __restrict__ W3,
                       const float* __restrict__ B0, const float* __restrict__ B1,
                       const float* __restrict__ B2, const float* __restrict__ B3)
{
    const int l = blockIdx.x, tid = threadIdx.x;
    const float* W  = (l == 0) ? W0 : (l == 1) ? W1 : (l == 2) ? W2 : W3;
    const float* Bb = (l == 0) ? B0 : (l == 1) ? B1 : (l == 2) ? B2 : B3;
    for (int idx = tid; idx < NW * 64; idx += 256) {
        int n = idx >> 6, k = idx & 63;
        int q = n / 48, r = n % 48;
        int j = r / 24, gate = (r % 24) >> 3, e = r & 7;
        int c = q * 16 + j * 8 + e;
        int gn = (gate == 0) ? c : (gate == 1) ? 128 + c : 192 + c;   // skip dead f gate
        uint32_t sw = (uint32_t)n * 64 + ((((uint32_t)(2 * k)) ^ (((uint32_t)n & 7) << 4)) >> 1);
        g_Wh[l][sw] = f2h(W[k * 256 + gn]);
    }
    for (int n = tid; n < NW; n += 256) {
        int q = n / 48, r = n % 48;
        int j = r / 24, gate = (r % 24) >> 3, e = r & 7;
        int c = q * 16 + j * 8 + e;
        int gn = (gate == 0) ? c : (gate == 1) ? 128 + c : 192 + c;
        g_Bp[l][n] = Bb[gn];
    }
}

// ---------------------------------------------------------------------------
// Kernel A: persistent fused 4x ConvLSTM via mma.sync fp16 SINGLE-PASS
// (A and B both single fp16; error budget measured: B-only quant gave 5.07e-4,
// A adds in quadrature -> ~7.2e-4 expected, under the 1e-3 threshold).
// 148 blocks x 512 threads = two independent 8-warp pipelines (named barriers).
// Warp tile 32m x 48n: 5 LDSM + 12 mma per ks, 4 ks per layer.
// ---------------------------------------------------------------------------
__global__ void __launch_bounds__(THR_A, 1) k_lstm4(const float* __restrict__ x)
{
    extern __shared__ char sm[];
    const uint32_t sb = smem_u32(sm);
    const int tid = threadIdx.x;
    const int wid = tid >> 5, lane = tid & 31;
    const int grp = tid >> 8;            // barrier group 0/1
    const int tig256 = tid & 255;        // tid within group
    const int g8 = lane >> 2, tig = lane & 3;

    // one-time: weights (96KB) + biases -> smem (all 512 threads)
    {
        const uint4* src = (const uint4*)g_Wh;
        uint4* dst = (uint4*)(sm + WOFF);
        #pragma unroll
        for (int i = 0; i < 12; ++i) dst[tid + i * THR_A] = src[tid + i * THR_A];
        float* bsw = (float*)(sm + BIAS);
        #pragma unroll
        for (int i = 0; i < 2; ++i) {
            int idx = tid + i * THR_A;
            if (idx < 4 * NW) bsw[idx] = ((const float*)g_Bp)[idx];
        }
    }
    __syncthreads();                     // weights immutable hereafter
    const float* bs = (const float*)(sm + BIAS);

    // group-local warp layout: 8 warps = 2 m-groups (32 rows) x 4 n-quarters (48 cols)
    const int wg = wid & 7;
    const int lt = lane >> 3, lr = lane & 7;
    const int mgrp = wg & 1, nq = wg >> 1;
    const int mrow = mgrp * 32, n0 = nq * 48, chb = nq * 16;
    const uint32_t AG = ABUF + (uint32_t)grp * 16384;   // group's buffer base
    const int arow = mrow + ((lt & 1) << 3) + lr;
    const uint32_t a_rowoff = (uint32_t)arow * 128;
    const uint32_t aswz = ((uint32_t)arow & 7) << 4;
    const int akadd = (lt >> 1) << 4;
    const int brow0 = n0 + ((lt >> 1) << 3) + lr;
    const uint32_t b_rowoff0 = (uint32_t)brow0 * 128;
    const uint32_t bswz = ((uint32_t)brow0 & 7) << 4;
    const int bkadd = (lt & 1) << 4;
    const int bar = grp + 1;

    for (int t = blockIdx.x * 2 + grp; t < NTILES; t += GRID_A * 2) {
        // stage input tile (single fp16) into buf0; overlaps prev tile's L3 mma
        {
            const float4* xin = (const float4*)(x + (size_t)t * MTILE * CH);
            #pragma unroll
            for (int i = 0; i < 4; ++i) {
                int fi = tig256 + i * 256;          // 1024 float4
                int pos = fi >> 4, c = (fi & 15) << 2;
                float4 v = xin[fi];
                uint32_t b = (uint32_t)pos * 128 + (((uint32_t)(2 * c)) ^ (((uint32_t)pos & 7) << 4));
                *(u64*)(sm + AG + b) = pack4hf(v.x, v.y, v.z, v.w);
            }
        }
        GBAR(bar);

        #pragma unroll 1
        for (int l = 0; l < 4; ++l) {
            const uint32_t rbuf = AG + (uint32_t)(l & 1) * 8192;        // read buf
            const uint32_t wbuf = AG + (uint32_t)((l + 1) & 1) * 8192;  // write buf

            float acc[2][6][4];
            #pragma unroll
            for (int mi = 0; mi < 2; ++mi)
                #pragma unroll
                for (int nt = 0; nt < 6; ++nt)
                    #pragma unroll
                    for (int r = 0; r < 4; ++r) acc[mi][nt][r] = 0.f;

            const uint32_t Babs = sb + WOFF + (uint32_t)l * WLSZ + b_rowoff0;
            const uint32_t Aabs = sb + rbuf + a_rowoff;
            #pragma unroll
            for (int ks = 0; ks < 4; ++ks) {
                const uint32_t kb = ks * 32;
                const uint32_t ka = (kb + akadd) ^ aswz;
                const uint32_t kbb = (kb + bkadd) ^ bswz;
                uint32_t b[3][4], a0[4], a1[4];
                #pragma unroll
                for (int np = 0; np < 3; ++np)
                    LDSM_X4(b[np], Babs + (uint32_t)np * 2048 + kbb);
                LDSM_X4(a0, Aabs + ka);
                LDSM_X4(a1, Aabs + 2048 + ka);       // +16 rows, same swizzle
                #pragma unroll
                for (int np = 0; np < 3; ++np) {
                    mma16816(acc[0][2 * np],     a0, b[np][0], b[np][1]);
                    mma16816(acc[0][2 * np + 1], a0, b[np][2], b[np][3]);
                    mma16816(acc[1][2 * np],     a1, b[np][0], b[np][1]);
                    mma16816(acc[1][2 * np + 1], a1, b[np][2], b[np][3]);
                }
            }

            // register gate epilogue: per mi, frags [3j]=i, [3j+1]=g, [3j+2]=o
            float hreg[2][2][4];
            const float* bl = bs + l * NW + n0 + 2 * tig;
            #pragma unroll
            for (int mi = 0; mi < 2; ++mi) {
                #pragma unroll
                for (int j = 0; j < 2; ++j) {
                    float2 bi = *(const float2*)(bl + j * 24);
                    float2 bg = *(const float2*)(bl + j * 24 + 8);
                    float2 bo = *(const float2*)(bl + j * 24 + 16);
                    const float* ai = acc[mi][3 * j];
                    const float* ag = acc[mi][3 * j + 1];
                    const float* ao = acc[mi][3 * j + 2];
                    hreg[mi][j][0] = hsig(ao[0] + bo.x) * tanh_fast(hsig(ai[0] + bi.x) * tanh_fast(ag[0] + bg.x));
                    hreg[mi][j][1] = hsig(ao[1] + bo.y) * tanh_fast(hsig(ai[1] + bi.y) * tanh_fast(ag[1] + bg.y));
                    hreg[mi][j][2] = hsig(ao[2] + bo.x) * tanh_fast(hsig(ai[2] + bi.x) * tanh_fast(ag[2] + bg.x));
                    hreg[mi][j][3] = hsig(ao[3] + bo.y) * tanh_fast(hsig(ai[3] + bi.y) * tanh_fast(ag[3] + bg.y));
                }
            }

            if (l < 3) {
                // ping-pong: write into wbuf (untouched by this layer's reads)
                #pragma unroll
                for (int mi = 0; mi < 2; ++mi) {
                    const int m1 = mrow + mi * 16 + g8, m2 = m1 + 8;
                    #pragma unroll
                    for (int j = 0; j < 2; ++j) {
                        int c0 = chb + j * 8 + 2 * tig;
                        const float* h = hreg[mi][j];
                        uint32_t b1o = (uint32_t)m1 * 128 + (((uint32_t)(2 * c0)) ^ (((uint32_t)m1 & 7) << 4));
                        uint32_t b2o = (uint32_t)m2 * 128 + (((uint32_t)(2 * c0)) ^ (((uint32_t)m2 & 7) << 4));
                        *(uint32_t*)(sm + wbuf + b1o) = pk2hf(h[0], h[1]);
                        *(uint32_t*)(sm + wbuf + b2o) = pk2hf(h[2], h[3]);
                    }
                }
                GBAR(bar);   // writes visible before next layer's reads
            } else {
                const size_t p0 = (size_t)t * MTILE;
                #pragma unroll
                for (int mi = 0; mi < 2; ++mi) {
                    const int m1 = mrow + mi * 16 + g8, m2 = m1 + 8;
                    #pragma unroll
                    for (int j = 0; j < 2; ++j) {
                        int c0 = chb + j * 8 + 2 * tig;
                        const float* h = hreg[mi][j];
                        *(float2*)&g_h4[(p0 + m1) * CH + c0] = make_float2(h[0], h[1]);
                        *(float2*)&g_h4[(p0 + m2) * CH + c0] = make_float2(h[2], h[3]);
                    }
                }
            }
        }
    }
}

// ---------------------------------------------------------------------------
// Kernel B: split-K GEMM via fp16 mma, 3-pass (AhBh + AlBh + AhBl ~ fp32-exact):
// partial[g] = flat[:, kb:kb+128] @ D1w[kb:kb+128, :].  M=64(batch) N=64 K=128.
// B row-major [k][n] staging (conflict-free), fragments via ldmatrix.trans.
// ---------------------------------------------------------------------------
#define DAH 0
#define DAL 16384
#define DBH 32768
#define DBL 49152
#define SMEM_B_TOT 65536

__global__ void __launch_bounds__(256) k_dense_split(const float* __restrict__ D1w)
{
    extern __shared__ char smf[];
    const uint32_t sb = smem_u32(smf);
    const int tid = threadIdx.x, wid = tid >> 5, lane = tid & 31;
    const size_t kbase = (size_t)blockIdx.x * KC;

    // A: g_h4 [64 b][128 k] fp32 -> hi/lo fp16, rows 256B, XOR swz
    #pragma unroll
    for (int i = 0; i < 8; ++i) {
        int fi = tid + i * 256;                 // 2048 float4
        int b = fi >> 5, kq = fi & 31;          // k = kq*4
        float4 v = *(const float4*)(g_h4 + (size_t)b * FLATK + kbase + (size_t)kq * 4);
        uint32_t off = (uint32_t)b * 256 + (((uint32_t)(kq * 8)) ^ (((uint32_t)b & 7) << 4));
        *(u64*)(smf + DAH + off) = pack4hf(v.x, v.y, v.z, v.w);
        *(u64*)(smf + DAL + off) = pack4hf(
            v.x - h2f(f2h(v.x)), v.y - h2f(f2h(v.y)),
            v.z - h2f(f2h(v.z)), v.w - h2f(f2h(v.w)));
    }
    // B: D1w [128 k][64 n] fp32 -> fp16 hi/lo ROW-MAJOR [k][n], rows 128B, XOR swz
    #pragma unroll
    for (int i = 0; i < 8; ++i) {
        int fi = tid + i * 256;                 // 2048 float4
        int k = fi >> 4, nq = fi & 15;          // n = nq*4
        float4 v = ((const float4*)(D1w + (kbase + k) * 64))[nq];
        uint32_t off = (uint32_t)k * 128 + (((uint32_t)(nq * 8)) ^ (((uint32_t)k & 7) << 4));
        *(u64*)(smf + DBH + off) = pack4hf(v.x, v.y, v.z, v.w);
        *(u64*)(smf + DBL + off) = pack4hf(
            v.x - h2f(f2h(v.x)), v.y - h2f(f2h(v.y)),
            v.z - h2f(f2h(v.z)), v.w - h2f(f2h(v.w)));
    }
    __syncthreads();

    // 8 warps: mw 0..3 (16 batch rows), nw 0..1 (32 n cols)
    const int mw = wid & 3, nw = wid >> 2;
    const int lt = lane >> 3, lr = lane & 7;
    const int g8 = lane >> 2, tig = lane & 3;
    const int arow = mw * 16 + ((lt & 1) << 3) + lr;
    const uint32_t a_ro = (uint32_t)arow * 256, aswz = ((uint32_t)arow & 7) << 4;
    const int akadd = (lt >> 1) << 4;
    const uint32_t b_row = (uint32_t)(((lt & 1) << 3) + lr) * 128;
    const uint32_t bksw = ((uint32_t)lr) << 4;
    const uint32_t bn0 = (uint32_t)(nw * 64) + ((uint32_t)(lt >> 1) << 4);

    float acc[4][4];
    #pragma unroll
    for (int nf = 0; nf < 4; ++nf)
        #pragma unroll
        for (int r = 0; r < 4; ++r) acc[nf][r] = 0.f;

    #pragma unroll
    for (int ks = 0; ks < 8; ++ks) {
        const uint32_t kb = ks * 32;
        const uint32_t ka = (kb + akadd) ^ aswz;
        const uint32_t bko = (uint32_t)ks * 2048 + b_row;
        uint32_t ah[4], al[4], bh0[4], bh1[4], bl0[4], bl1[4];
        LDSM_X4(ah, sb + DAH + a_ro + ka);
        LDSM_X4(al, sb + DAL + a_ro + ka);
        LDSM_X4T(bh0, sb + DBH + bko + (bn0 ^ bksw));
        LDSM_X4T(bh1, sb + DBH + bko + ((bn0 + 32) ^ bksw));   // +16 n
        LDSM_X4T(bl0, sb + DBL + bko + (bn0 ^ bksw));
        LDSM_X4T(bl1, sb + DBL + bko + ((bn0 + 32) ^ bksw));
        mma16816(acc[0], ah, bh0[0], bh0[1]);
        mma16816(acc[1], ah, bh0[2], bh0[3]);
        mma16816(acc[2], ah, bh1[0], bh1[1]);
        mma16816(acc[3], ah, bh1[2], bh1[3]);
        mma16816(acc[0], al, bh0[0], bh0[1]);
        mma16816(acc[1], al, bh0[2], bh0[3]);
        mma16816(acc[2], al, bh1[0], bh1[1]);
        mma16816(acc[3], al, bh1[2], bh1[3]);
        mma16816(acc[0], ah, bl0[0], bl0[1]);
        mma16816(acc[1], ah, bl0[2], bl0[3]);
        mma16816(acc[2], ah, bl1[0], bl1[1]);
        mma16816(acc[3], ah, bl1[2], bl1[3]);
    }

    float* dst = g_part + (size_t)blockIdx.x * 4096;
    const int m1 = mw * 16 + g8, m2 = m1 + 8;
    #pragma unroll
    for (int nf = 0; nf < 4; ++nf) {
        int n = nw * 32 + nf * 8 + 2 * tig;
        *(float2*)&dst[m1 * 64 + n] = make_float2(acc[nf][0], acc[nf][1]);
        *(float2*)&dst[m2 * 64 + n] = make_float2(acc[nf][2], acc[nf][3]);
    }
}

// ---------------------------------------------------------------------------
// Kernel C1: stage-1 reduce: 2048 blocks, each sums 32 g-slices for (b,chunk).
// ---------------------------------------------------------------------------
__global__ void k_red1()
{
    __shared__ float sred[256];
    const int blk = blockIdx.x;            // 2048 = 64 b x 32 chunks
    const int b = blk >> 5, chunk = blk & 31;
    const int tid = threadIdx.x;
    const int n = tid & 63, sub = tid >> 6;
    const float* p = g_part + (size_t)(chunk * 32 + sub * 8) * 4096 + (size_t)b * 64 + n;
    float s = 0.f;
    #pragma unroll
    for (int t = 0; t < 8; ++t) s += p[(size_t)t * 4096];
    sred[tid] = s;
    __syncthreads();
    if (tid < 64)
        g_red[chunk * 4096 + b * 64 + n] =
            sred[tid] + sred[tid + 64] + sred[tid + 128] + sred[tid + 192];
}

// ---------------------------------------------------------------------------
// Kernel C2: final: sum 32 chunks + D1b + relu + D2 GEMV. 64 blocks x 64 thr.
// ---------------------------------------------------------------------------
__global__ void k_final(const float* __restrict__ D1b, const float* __restrict__ D2w,
                        const float* __restrict__ D2b, float* __restrict__ out)
{
    __shared__ float sA[2];
    const int b = blockIdx.x, n = threadIdx.x;   // 64 threads
    float v = 0.f;
    #pragma unroll
    for (int ch = 0; ch < RCH; ++ch) v += g_red[ch * 4096 + b * 64 + n];
    float y = fmaxf(v + D1b[n], 0.f) * D2w[n];
    #pragma unroll
    for (int off = 16; off > 0; off >>= 1)
        y += __shfl_down_sync(0xffffffffu, y, off);
    if ((n & 31) == 0) sA[n >> 5] = y;
    __syncthreads();
    if (n == 0) out[b] = sA[0] + sA[1] + D2b[0];
}

// ---------------------------------------------------------------------------
extern "C" void kernel_launch(void* const* d_in, const int* in_sizes, int n_in,
                              void* d_out, int out_size)
{
    const float* x   = (const float*)d_in[0];
    const float* W1x = (const float*)d_in[1];
    const float* b1  = (const float*)d_in[3];
    const float* W2x = (const float*)d_in[4];
    const float* b2  = (const float*)d_in[6];
    const float* W3x = (const float*)d_in[7];
    const float* b3  = (const float*)d_in[9];
    const float* W4x = (const float*)d_in[10];
    const float* b4  = (const float*)d_in[12];
    const float* D1w = (const float*)d_in[13];
    const float* D1b = (const float*)d_in[14];
    const float* D2w = (const float*)d_in[15];
    const float* D2b = (const float*)d_in[16];

    cudaFuncSetAttribute(k_lstm4, cudaFuncAttributeMaxDynamicSharedMemorySize, SMEM_A_TOT);
    cudaFuncSetAttribute(k_dense_split, cudaFuncAttributeMaxDynamicSharedMemorySize, SMEM_B_TOT);

    // SAME padding over H=1 picks exactly one kernel row: r=4 (kh=10), r=2 (kh=5)
    k_prep<<<4, 256>>>(W1x + 4 * 64 * 256, W2x + 2 * 64 * 256,
                       W3x + 4 * 64 * 256, W4x + 2 * 64 * 256,
                       b1, b2, b3, b4);
    k_lstm4<<<GRID_A, THR_A, SMEM_A_TOT>>>(x);
    k_dense_split<<<GSPLIT, 256, SMEM_B_TOT>>>(D1w);
    k_red1<<<2048, 256>>>();
    k_final<<<BATCH, 64>>>(D1b, D2w, D2b, (float*)d_out);
}